// round 2
// baseline (speedup 1.0000x reference)
#include <cuda_runtime.h>

// Problem dims
#define BB  2
#define SS  2048
#define HH  1024
#define NHH 16
#define HDD 64
#define MM  (BB*SS)          // 4096 rows

// ---------------- scratch (no cudaMalloc allowed) ----------------
__device__ float g_wq[HH*HH];
__device__ float g_wk[HH*HH];
__device__ float g_wv[HH*HH];
__device__ float g_wo[HH*HH];
__device__ float g_q[MM*HH];
__device__ float g_k[MM*HH];
__device__ float g_v[MM*HH];
__device__ float g_attn[MM*HH];

// ---------------- W = static + dynamic ----------------
__global__ void wadd_kernel(const float* __restrict__ a,
                            const float* __restrict__ b,
                            float* __restrict__ w) {
    int i = blockIdx.x * blockDim.x + threadIdx.x;
    float4 x = ((const float4*)a)[i];
    float4 y = ((const float4*)b)[i];
    ((float4*)w)[i] = make_float4(x.x + y.x, x.y + y.y, x.z + y.z, x.w + y.w);
}

// ---------------- C[4096,1024] = A[4096,1024] @ W[1024,1024]^T ----------------
// 128x128 tile, BK=16, 256 threads, 8x8 per thread, reg-prefetch single smem buffer.
__global__ __launch_bounds__(256, 2)
void sgemm_kernel(const float* __restrict__ A, const float* __restrict__ W,
                  float* __restrict__ C) {
    constexpr int K = 1024, N = 1024;
    __shared__ float a_s[16][132];
    __shared__ float b_s[16][132];

    const int tid = threadIdx.x;
    const int m0 = blockIdx.y * 128;
    const int n0 = blockIdx.x * 128;
    const int ty = tid >> 4, tx = tid & 15;
    const int r0 = tid >> 2;              // 0..63 (and +64)
    const int c0 = (tid & 3) * 4;         // 0,4,8,12

    const float* Ap = A + (size_t)(m0 + r0) * K + c0;
    const float* Wp = W + (size_t)(n0 + r0) * K + c0;

    float4 fa0 = *(const float4*)(Ap);
    float4 fa1 = *(const float4*)(Ap + 64 * K);
    float4 fb0 = *(const float4*)(Wp);
    float4 fb1 = *(const float4*)(Wp + 64 * K);

    float acc[8][8];
#pragma unroll
    for (int i = 0; i < 8; i++)
#pragma unroll
        for (int j = 0; j < 8; j++) acc[i][j] = 0.f;

    for (int kt = 0; kt < K; kt += 16) {
        a_s[c0 + 0][r0] = fa0.x; a_s[c0 + 1][r0] = fa0.y;
        a_s[c0 + 2][r0] = fa0.z; a_s[c0 + 3][r0] = fa0.w;
        a_s[c0 + 0][r0 + 64] = fa1.x; a_s[c0 + 1][r0 + 64] = fa1.y;
        a_s[c0 + 2][r0 + 64] = fa1.z; a_s[c0 + 3][r0 + 64] = fa1.w;
        b_s[c0 + 0][r0] = fb0.x; b_s[c0 + 1][r0] = fb0.y;
        b_s[c0 + 2][r0] = fb0.z; b_s[c0 + 3][r0] = fb0.w;
        b_s[c0 + 0][r0 + 64] = fb1.x; b_s[c0 + 1][r0 + 64] = fb1.y;
        b_s[c0 + 2][r0 + 64] = fb1.z; b_s[c0 + 3][r0 + 64] = fb1.w;
        __syncthreads();

        if (kt + 16 < K) {
            fa0 = *(const float4*)(Ap + kt + 16);
            fa1 = *(const float4*)(Ap + 64 * K + kt + 16);
            fb0 = *(const float4*)(Wp + kt + 16);
            fb1 = *(const float4*)(Wp + 64 * K + kt + 16);
        }

#pragma unroll
        for (int k = 0; k < 16; k++) {
            float af[8], bf[8];
#pragma unroll
            for (int i = 0; i < 8; i++) af[i] = a_s[k][ty * 8 + i];
#pragma unroll
            for (int j = 0; j < 8; j++) bf[j] = b_s[k][tx * 8 + j];
#pragma unroll
            for (int i = 0; i < 8; i++)
#pragma unroll
                for (int j = 0; j < 8; j++)
                    acc[i][j] = fmaf(af[i], bf[j], acc[i][j]);
        }
        __syncthreads();
    }

#pragma unroll
    for (int i = 0; i < 8; i++) {
        float* cp = C + (size_t)(m0 + ty * 8 + i) * N + n0 + tx * 8;
        *(float4*)(cp)     = make_float4(acc[i][0], acc[i][1], acc[i][2], acc[i][3]);
        *(float4*)(cp + 4) = make_float4(acc[i][4], acc[i][5], acc[i][6], acc[i][7]);
    }
}

// ---------------- flash attention, fp32 ----------------
// grid: (S/128, NH, B). 256 threads. Per block: Q tile 128xHD, loop K tiles of 128.
#define PSTR 132
#define ATTN_SMEM ((64*128 + 128*PSTR + 128*64) * 4)

__global__ __launch_bounds__(256, 1)
void attn_kernel(const float* __restrict__ mask) {
    extern __shared__ float sm[];
    float* q_s  = sm;                       // [HD][128]  k-major
    float* kp_s = sm + 64 * 128;            // union: K tile [HD][128] / P tile [128][PSTR]
    float* v_s  = kp_s + 128 * PSTR;        // [128][HD]

    const int tid = threadIdx.x;
    const int ty = tid >> 4, tx = tid & 15;
    const int b = blockIdx.z, h = blockIdx.y;
    const int q0 = blockIdx.x * 128;

    const float* qbase = g_q + (size_t)(b * SS) * HH + h * HDD;
    const float* kbase = g_k + (size_t)(b * SS) * HH + h * HDD;
    const float* vbase = g_v + (size_t)(b * SS) * HH + h * HDD;
    const float* mbase = mask + (size_t)b * SS * SS;

    // load Q tile -> q_s[d][m]
#pragma unroll
    for (int t = 0; t < 8; t++) {
        int idx = tid + t * 256;            // 0..2047
        int m = idx >> 4;
        int d = (idx & 15) * 4;
        float4 v = *(const float4*)(qbase + (size_t)(q0 + m) * HH + d);
        q_s[(d + 0) * 128 + m] = v.x;
        q_s[(d + 1) * 128 + m] = v.y;
        q_s[(d + 2) * 128 + m] = v.z;
        q_s[(d + 3) * 128 + m] = v.w;
    }

    float o[8][4];
    float mrow[8], lrow[8];
#pragma unroll
    for (int i = 0; i < 8; i++) {
        mrow[i] = -INFINITY; lrow[i] = 0.f;
#pragma unroll
        for (int jj = 0; jj < 4; jj++) o[i][jj] = 0.f;
    }

    for (int kt = 0; kt < SS; kt += 128) {
        __syncthreads();  // prev PV done (also fences Q-load on first iter)

        // load K -> kp_s[d][n], V -> v_s[n][d]
#pragma unroll
        for (int t = 0; t < 8; t++) {
            int idx = tid + t * 256;
            int n = idx >> 4;
            int d = (idx & 15) * 4;
            float4 kv = *(const float4*)(kbase + (size_t)(kt + n) * HH + d);
            kp_s[(d + 0) * 128 + n] = kv.x;
            kp_s[(d + 1) * 128 + n] = kv.y;
            kp_s[(d + 2) * 128 + n] = kv.z;
            kp_s[(d + 3) * 128 + n] = kv.w;
            float4 vv = *(const float4*)(vbase + (size_t)(kt + n) * HH + d);
            *(float4*)(v_s + n * 64 + d) = vv;
        }
        __syncthreads();

        // S = Q K^T
        float s[8][8];
#pragma unroll
        for (int i = 0; i < 8; i++)
#pragma unroll
            for (int j = 0; j < 8; j++) s[i][j] = 0.f;

#pragma unroll 4
        for (int d = 0; d < 64; d++) {
            float4 a0 = *(const float4*)(q_s + d * 128 + ty * 8);
            float4 a1 = *(const float4*)(q_s + d * 128 + ty * 8 + 4);
            float4 b0 = *(const float4*)(kp_s + d * 128 + tx * 8);
            float4 b1 = *(const float4*)(kp_s + d * 128 + tx * 8 + 4);
            float af[8] = {a0.x, a0.y, a0.z, a0.w, a1.x, a1.y, a1.z, a1.w};
            float bf[8] = {b0.x, b0.y, b0.z, b0.w, b1.x, b1.y, b1.z, b1.w};
#pragma unroll
            for (int i = 0; i < 8; i++)
#pragma unroll
                for (int j = 0; j < 8; j++)
                    s[i][j] = fmaf(af[i], bf[j], s[i][j]);
        }

        // scale + mask + online softmax
#pragma unroll
        for (int i = 0; i < 8; i++) {
            const float* mr = mbase + (size_t)(q0 + ty * 8 + i) * SS + kt + tx * 8;
            float4 mk0 = *(const float4*)(mr);
            float4 mk1 = *(const float4*)(mr + 4);
            s[i][0] = s[i][0] * 0.125f + mk0.x;
            s[i][1] = s[i][1] * 0.125f + mk0.y;
            s[i][2] = s[i][2] * 0.125f + mk0.z;
            s[i][3] = s[i][3] * 0.125f + mk0.w;
            s[i][4] = s[i][4] * 0.125f + mk1.x;
            s[i][5] = s[i][5] * 0.125f + mk1.y;
            s[i][6] = s[i][6] * 0.125f + mk1.z;
            s[i][7] = s[i][7] * 0.125f + mk1.w;

            float rm = s[i][0];
#pragma unroll
            for (int j = 1; j < 8; j++) rm = fmaxf(rm, s[i][j]);
#pragma unroll
            for (int off = 8; off >= 1; off >>= 1)
                rm = fmaxf(rm, __shfl_xor_sync(0xffffffffu, rm, off));

            float nm = fmaxf(mrow[i], rm);
            float corr = __expf(mrow[i] - nm);
            float rs = 0.f;
#pragma unroll
            for (int j = 0; j < 8; j++) {
                s[i][j] = __expf(s[i][j] - nm);
                rs += s[i][j];
            }
#pragma unroll
            for (int off = 8; off >= 1; off >>= 1)
                rs += __shfl_xor_sync(0xffffffffu, rs, off);

            lrow[i] = lrow[i] * corr + rs;
            mrow[i] = nm;
#pragma unroll
            for (int jj = 0; jj < 4; jj++) o[i][jj] *= corr;
        }

        __syncthreads();  // done reading K from kp_s

        // write P tile (reuse kp_s region)
#pragma unroll
        for (int i = 0; i < 8; i++) {
            float* pp = kp_s + (ty * 8 + i) * PSTR + tx * 8;
            *(float4*)(pp)     = make_float4(s[i][0], s[i][1], s[i][2], s[i][3]);
            *(float4*)(pp + 4) = make_float4(s[i][4], s[i][5], s[i][6], s[i][7]);
        }
        __syncthreads();

        // O += P V
#pragma unroll 2
        for (int n = 0; n < 128; n += 4) {
            float4 pr[8];
#pragma unroll
            for (int i = 0; i < 8; i++)
                pr[i] = *(const float4*)(kp_s + (ty * 8 + i) * PSTR + n);
#pragma unroll
            for (int nn = 0; nn < 4; nn++) {
                float4 vv = *(const float4*)(v_s + (n + nn) * 64 + tx * 4);
#pragma unroll
                for (int i = 0; i < 8; i++) {
                    float p = (nn == 0) ? pr[i].x : (nn == 1) ? pr[i].y
                            : (nn == 2) ? pr[i].z : pr[i].w;
                    o[i][0] = fmaf(p, vv.x, o[i][0]);
                    o[i][1] = fmaf(p, vv.y, o[i][1]);
                    o[i][2] = fmaf(p, vv.z, o[i][2]);
                    o[i][3] = fmaf(p, vv.w, o[i][3]);
                }
            }
        }
    }

    // normalize + store
#pragma unroll
    for (int i = 0; i < 8; i++) {
        float inv = 1.f / lrow[i];
        float* op = g_attn + (size_t)(b * SS + q0 + ty * 8 + i) * HH + h * HDD + tx * 4;
        *(float4*)op = make_float4(o[i][0] * inv, o[i][1] * inv, o[i][2] * inv, o[i][3] * inv);
    }
}

// ---------------- launch ----------------
extern "C" void kernel_launch(void* const* d_in, const int* in_sizes, int n_in,
                              void* d_out, int out_size) {
    (void)in_sizes; (void)n_in; (void)out_size;
    const float* hidden = (const float*)d_in[0];
    const float* mask   = (const float*)d_in[1];
    const float* qs = (const float*)d_in[2];
    const float* qd = (const float*)d_in[3];
    const float* ks = (const float*)d_in[4];
    const float* kd = (const float*)d_in[5];
    const float* vs = (const float*)d_in[6];
    const float* vd = (const float*)d_in[7];
    const float* os = (const float*)d_in[8];
    const float* od = (const float*)d_in[9];

    float *wq, *wk, *wv, *wo, *q, *k, *v, *attn;
    cudaGetSymbolAddress((void**)&wq, g_wq);
    cudaGetSymbolAddress((void**)&wk, g_wk);
    cudaGetSymbolAddress((void**)&wv, g_wv);
    cudaGetSymbolAddress((void**)&wo, g_wo);
    cudaGetSymbolAddress((void**)&q,  g_q);
    cudaGetSymbolAddress((void**)&k,  g_k);
    cudaGetSymbolAddress((void**)&v,  g_v);
    cudaGetSymbolAddress((void**)&attn, g_attn);

    const int wblocks = (HH * HH / 4) / 256;  // 1024 blocks
    wadd_kernel<<<wblocks, 256>>>(qs, qd, wq);
    wadd_kernel<<<wblocks, 256>>>(ks, kd, wk);
    wadd_kernel<<<wblocks, 256>>>(vs, vd, wv);
    wadd_kernel<<<wblocks, 256>>>(os, od, wo);

    dim3 ggrid(HH / 128, MM / 128);  // (8, 32)
    sgemm_kernel<<<ggrid, 256>>>(hidden, wq, q);
    sgemm_kernel<<<ggrid, 256>>>(hidden, wk, k);
    sgemm_kernel<<<ggrid, 256>>>(hidden, wv, v);

    cudaFuncSetAttribute(attn_kernel,
                         cudaFuncAttributeMaxDynamicSharedMemorySize, ATTN_SMEM);
    attn_kernel<<<dim3(SS / 128, NHH, BB), 256, ATTN_SMEM>>>(mask);

    sgemm_kernel<<<ggrid, 256>>>(attn, wo, (float*)d_out);
}

// round 4
// speedup vs baseline: 1.1175x; 1.1175x over previous
#include <cuda_runtime.h>
#include <cuda_bf16.h>
#include <cstdint>

// Problem dims
#define BB  2
#define SS  2048
#define HH  1024
#define NHH 16
#define HDD 64
#define MM  (BB*SS)          // 4096 rows

// ---------------- scratch (no cudaMalloc allowed) ----------------
__device__ __nv_bfloat16 g_a2[MM * 2048];        // [4096, 2048] hi|lo split of activations
__device__ __nv_bfloat16 g_wq2[HH * 2048];       // [1024, 2048] hi|lo split of W
__device__ __nv_bfloat16 g_wk2[HH * 2048];
__device__ __nv_bfloat16 g_wv2[HH * 2048];
__device__ __nv_bfloat16 g_wo2[HH * 2048];
__device__ float g_q[MM*HH];
__device__ float g_k[MM*HH];
__device__ float g_v[MM*HH];
__device__ float g_attn[MM*HH];

// ================= PTX helpers (non-'a' features only) =================
__device__ __forceinline__ uint32_t smem_u32(const void* p) {
    uint32_t a;
    asm("{ .reg .u64 t; cvta.to.shared.u64 t, %1; cvt.u32.u64 %0, t; }" : "=r"(a) : "l"(p));
    return a;
}
__device__ __forceinline__ void cp16(uint32_t dst, const void* src) {
    asm volatile("cp.async.cg.shared.global [%0], [%1], 16;" :: "r"(dst), "l"(src));
}
__device__ __forceinline__ void cp_commit() {
    asm volatile("cp.async.commit_group;" ::: "memory");
}
__device__ __forceinline__ void cp_wait1() {
    asm volatile("cp.async.wait_group 1;" ::: "memory");
}
__device__ __forceinline__ void cp_wait0() {
    asm volatile("cp.async.wait_group 0;" ::: "memory");
}
__device__ __forceinline__ void ldmat4(uint32_t& r0, uint32_t& r1, uint32_t& r2, uint32_t& r3,
                                       uint32_t addr) {
    asm volatile("ldmatrix.sync.aligned.m8n8.x4.shared.b16 {%0,%1,%2,%3}, [%4];"
                 : "=r"(r0), "=r"(r1), "=r"(r2), "=r"(r3) : "r"(addr));
}
__device__ __forceinline__ void mma16816(float* d, uint32_t a0, uint32_t a1, uint32_t a2,
                                         uint32_t a3, uint32_t b0, uint32_t b1) {
    asm volatile("mma.sync.aligned.m16n8k16.row.col.f32.bf16.bf16.f32 "
                 "{%0,%1,%2,%3},{%4,%5,%6,%7},{%8,%9},{%0,%1,%2,%3};"
                 : "+f"(d[0]), "+f"(d[1]), "+f"(d[2]), "+f"(d[3])
                 : "r"(a0), "r"(a1), "r"(a2), "r"(a3), "r"(b0), "r"(b1));
}

// ================= split: out[r][0:1024]=bf16hi(a[+b]), out[r][1024:2048]=bf16lo =================
__global__ void split_kernel(const float* __restrict__ a, const float* __restrict__ b,
                             __nv_bfloat16* __restrict__ out) {
    int i = blockIdx.x * 256 + threadIdx.x;      // float4 index over [rows,1024]
    int r = i >> 8;
    int c4 = (i & 255) << 2;
    float4 x = ((const float4*)a)[i];
    if (b) {
        float4 y = ((const float4*)b)[i];
        x.x += y.x; x.y += y.y; x.z += y.z; x.w += y.w;
    }
    float vf[4] = {x.x, x.y, x.z, x.w};
    __nv_bfloat16 h[4], l[4];
#pragma unroll
    for (int j = 0; j < 4; j++) {
        h[j] = __float2bfloat16_rn(vf[j]);
        l[j] = __float2bfloat16_rn(vf[j] - __bfloat162float(h[j]));
    }
    __nv_bfloat16* o = out + (size_t)r * 2048 + c4;
    ((__nv_bfloat162*)o)[0] = __halves2bfloat162(h[0], h[1]);
    ((__nv_bfloat162*)o)[1] = __halves2bfloat162(h[2], h[3]);
    ((__nv_bfloat162*)(o + 1024))[0] = __halves2bfloat162(l[0], l[1]);
    ((__nv_bfloat162*)(o + 1024))[1] = __halves2bfloat162(l[2], l[3]);
}

// ================= HMMA split-bf16 GEMM =================
// C[4096,1024] = A[4096,1024] @ W[1024,1024]^T via hi/lo split (3 terms, K-concat 3072).
// CTA tile 128x128, 256 thr (8 warps, warp tile 32x64), K-chunk 32 bf16, double-buffered
// cp.async. Smem rows padded to 80B: 16B-unit index (5r mod 8) bijective -> conflict-free.
#define ROWB 80
#define TILEB (128 * ROWB)               // 10240 per matrix
#define STAGEB (2 * TILEB)               // 20480 per stage
#define NCH 96                           // 3 terms x 32 k32-chunks

__global__ __launch_bounds__(256, 1)
void tc_gemm(const __nv_bfloat16* __restrict__ A2,
             const __nv_bfloat16* __restrict__ W2q,
             const __nv_bfloat16* __restrict__ W2k,
             const __nv_bfloat16* __restrict__ W2v,
             float* __restrict__ Cq, float* __restrict__ Ck, float* __restrict__ Cv) {
    __shared__ __align__(128) char smbuf[2 * STAGEB];
    const uint32_t sbase = smem_u32(smbuf);

    const __nv_bfloat16* W2 = (blockIdx.z == 0) ? W2q : (blockIdx.z == 1) ? W2k : W2v;
    float* C = (blockIdx.z == 0) ? Cq : (blockIdx.z == 1) ? Ck : Cv;

    const int tid = threadIdx.x;
    const int wid = tid >> 5;
    const int lane = tid & 31;
    const int m0 = blockIdx.y * 128;
    const int n0 = blockIdx.x * 128;

    // ---- loader mapping: tid<128 -> A rows, else W rows; 64B (4x16B) per row-chunk ----
    const int isA = (tid < 128);
    const int lrow128 = isA ? tid : (tid - 128);
    const __nv_bfloat16* gbase = isA ? (A2 + (size_t)(m0 + lrow128) * 2048)
                                     : (W2 + (size_t)(n0 + lrow128) * 2048);
    const uint32_t sdst0 = sbase + (isA ? 0 : TILEB) + lrow128 * ROWB;

    // per-term column offsets: term0 hi*hi, term1 Ahi*Wlo, term2 Alo*Whi
    const int offT[3] = { 0, isA ? 0 : 1024, isA ? 1024 : 0 };

    // ---- ldmatrix lane addressing ----
    const int mi = lane >> 3, rr = lane & 7;
    const int lmrow = (mi & 1) * 8 + rr;     // row within 16-block
    const int lmunit = (mi >> 1);            // 16B unit within k16 (0/1)
    const int wm = wid >> 1;                 // 0..3  -> m offset wm*32
    const int wn = wid & 1;                  // 0..1  -> n offset wn*64

    float acc[2][8][4];
#pragma unroll
    for (int am = 0; am < 2; am++)
#pragma unroll
        for (int bn = 0; bn < 8; bn++)
#pragma unroll
            for (int j = 0; j < 4; j++) acc[am][bn][j] = 0.f;

    // prefetch chunk 0 -> stage 0
    {
        const __nv_bfloat16* src = gbase + 0;
#pragma unroll
        for (int q = 0; q < 4; q++) cp16(sdst0 + q * 16, src + q * 8);
        cp_commit();
    }

    for (int c = 0; c < NCH; ++c) {
        const int cur = c & 1;
        if (c + 1 < NCH) {
            const int cn = c + 1;
            const int t = cn >> 5, kc = cn & 31;
            const __nv_bfloat16* src = gbase + offT[t] + kc * 32;
            const uint32_t d = sdst0 + (cur ^ 1) * STAGEB;
#pragma unroll
            for (int q = 0; q < 4; q++) cp16(d + q * 16, src + q * 8);
            cp_commit();
            cp_wait1();
        } else {
            cp_wait0();
        }
        __syncthreads();

        // ---- compute on stage cur: 2 k16 steps ----
        const uint32_t sA = sbase + cur * STAGEB;
        const uint32_t sB = sA + TILEB;
#pragma unroll
        for (int kb = 0; kb < 2; kb++) {
            uint32_t a[2][4];
#pragma unroll
            for (int am = 0; am < 2; am++)
                ldmat4(a[am][0], a[am][1], a[am][2], a[am][3],
                       sA + (wm * 32 + am * 16 + lmrow) * ROWB + (kb * 2 + lmunit) * 16);
            uint32_t b0[8], b1[8];
#pragma unroll
            for (int bb = 0; bb < 4; bb++) {
                uint32_t r0, r1, r2, r3;
                ldmat4(r0, r1, r2, r3,
                       sB + (wn * 64 + bb * 16 + lmrow) * ROWB + (kb * 2 + lmunit) * 16);
                b0[bb * 2] = r0;     b1[bb * 2] = r2;
                b0[bb * 2 + 1] = r1; b1[bb * 2 + 1] = r3;
            }
#pragma unroll
            for (int am = 0; am < 2; am++)
#pragma unroll
                for (int bn = 0; bn < 8; bn++)
                    mma16816(acc[am][bn], a[am][0], a[am][1], a[am][2], a[am][3],
                             b0[bn], b1[bn]);
        }
        __syncthreads();
    }

    // ---- epilogue: fragment -> C ----
    const int g = lane >> 2, it = lane & 3;
#pragma unroll
    for (int am = 0; am < 2; am++) {
        const int row = m0 + wm * 32 + am * 16 + g;
#pragma unroll
        for (int bn = 0; bn < 8; bn++) {
            const int col = n0 + wn * 64 + bn * 8 + it * 2;
            float* p0 = C + (size_t)row * 1024 + col;
            float* p1 = p0 + 8 * 1024;
            *(float2*)p0 = make_float2(acc[am][bn][0], acc[am][bn][1]);
            *(float2*)p1 = make_float2(acc[am][bn][2], acc[am][bn][3]);
        }
    }
}

// ---------------- flash attention, fp32 (unchanged from R2) ----------------
#define PSTR 132
#define ATTN_SMEM ((64*128 + 128*PSTR + 128*64) * 4)

__global__ __launch_bounds__(256, 1)
void attn_kernel(const float* __restrict__ mask) {
    extern __shared__ float sm[];
    float* q_s  = sm;                       // [HD][128]  k-major
    float* kp_s = sm + 64 * 128;            // union: K tile [HD][128] / P tile [128][PSTR]
    float* v_s  = kp_s + 128 * PSTR;        // [128][HD]

    const int tid = threadIdx.x;
    const int ty = tid >> 4, tx = tid & 15;
    const int b = blockIdx.z, h = blockIdx.y;
    const int q0 = blockIdx.x * 128;

    const float* qbase = g_q + (size_t)(b * SS) * HH + h * HDD;
    const float* kbase = g_k + (size_t)(b * SS) * HH + h * HDD;
    const float* vbase = g_v + (size_t)(b * SS) * HH + h * HDD;
    const float* mbase = mask + (size_t)b * SS * SS;

#pragma unroll
    for (int t = 0; t < 8; t++) {
        int idx = tid + t * 256;
        int m = idx >> 4;
        int d = (idx & 15) * 4;
        float4 v = *(const float4*)(qbase + (size_t)(q0 + m) * HH + d);
        q_s[(d + 0) * 128 + m] = v.x;
        q_s[(d + 1) * 128 + m] = v.y;
        q_s[(d + 2) * 128 + m] = v.z;
        q_s[(d + 3) * 128 + m] = v.w;
    }

    float o[8][4];
    float mrow[8], lrow[8];
#pragma unroll
    for (int i = 0; i < 8; i++) {
        mrow[i] = -INFINITY; lrow[i] = 0.f;
#pragma unroll
        for (int jj = 0; jj < 4; jj++) o[i][jj] = 0.f;
    }

    for (int kt = 0; kt < SS; kt += 128) {
        __syncthreads();

#pragma unroll
        for (int t = 0; t < 8; t++) {
            int idx = tid + t * 256;
            int n = idx >> 4;
            int d = (idx & 15) * 4;
            float4 kv = *(const float4*)(kbase + (size_t)(kt + n) * HH + d);
            kp_s[(d + 0) * 128 + n] = kv.x;
            kp_s[(d + 1) * 128 + n] = kv.y;
            kp_s[(d + 2) * 128 + n] = kv.z;
            kp_s[(d + 3) * 128 + n] = kv.w;
            float4 vv = *(const float4*)(vbase + (size_t)(kt + n) * HH + d);
            *(float4*)(v_s + n * 64 + d) = vv;
        }
        __syncthreads();

        float s[8][8];
#pragma unroll
        for (int i = 0; i < 8; i++)
#pragma unroll
            for (int j = 0; j < 8; j++) s[i][j] = 0.f;

#pragma unroll 4
        for (int d = 0; d < 64; d++) {
            float4 a0 = *(const float4*)(q_s + d * 128 + ty * 8);
            float4 a1 = *(const float4*)(q_s + d * 128 + ty * 8 + 4);
            float4 b0 = *(const float4*)(kp_s + d * 128 + tx * 8);
            float4 b1 = *(const float4*)(kp_s + d * 128 + tx * 8 + 4);
            float af[8] = {a0.x, a0.y, a0.z, a0.w, a1.x, a1.y, a1.z, a1.w};
            float bf[8] = {b0.x, b0.y, b0.z, b0.w, b1.x, b1.y, b1.z, b1.w};
#pragma unroll
            for (int i = 0; i < 8; i++)
#pragma unroll
                for (int j = 0; j < 8; j++)
                    s[i][j] = fmaf(af[i], bf[j], s[i][j]);
        }

#pragma unroll
        for (int i = 0; i < 8; i++) {
            const float* mr = mbase + (size_t)(q0 + ty * 8 + i) * SS + kt + tx * 8;
            float4 mk0 = *(const float4*)(mr);
            float4 mk1 = *(const float4*)(mr + 4);
            s[i][0] = s[i][0] * 0.125f + mk0.x;
            s[i][1] = s[i][1] * 0.125f + mk0.y;
            s[i][2] = s[i][2] * 0.125f + mk0.z;
            s[i][3] = s[i][3] * 0.125f + mk0.w;
            s[i][4] = s[i][4] * 0.125f + mk1.x;
            s[i][5] = s[i][5] * 0.125f + mk1.y;
            s[i][6] = s[i][6] * 0.125f + mk1.z;
            s[i][7] = s[i][7] * 0.125f + mk1.w;

            float rm = s[i][0];
#pragma unroll
            for (int j = 1; j < 8; j++) rm = fmaxf(rm, s[i][j]);
#pragma unroll
            for (int off = 8; off >= 1; off >>= 1)
                rm = fmaxf(rm, __shfl_xor_sync(0xffffffffu, rm, off));

            float nm = fmaxf(mrow[i], rm);
            float corr = __expf(mrow[i] - nm);
            float rs = 0.f;
#pragma unroll
            for (int j = 0; j < 8; j++) {
                s[i][j] = __expf(s[i][j] - nm);
                rs += s[i][j];
            }
#pragma unroll
            for (int off = 8; off >= 1; off >>= 1)
                rs += __shfl_xor_sync(0xffffffffu, rs, off);

            lrow[i] = lrow[i] * corr + rs;
            mrow[i] = nm;
#pragma unroll
            for (int jj = 0; jj < 4; jj++) o[i][jj] *= corr;
        }

        __syncthreads();

#pragma unroll
        for (int i = 0; i < 8; i++) {
            float* pp = kp_s + (ty * 8 + i) * PSTR + tx * 8;
            *(float4*)(pp)     = make_float4(s[i][0], s[i][1], s[i][2], s[i][3]);
            *(float4*)(pp + 4) = make_float4(s[i][4], s[i][5], s[i][6], s[i][7]);
        }
        __syncthreads();

#pragma unroll 2
        for (int n = 0; n < 128; n += 4) {
            float4 pr[8];
#pragma unroll
            for (int i = 0; i < 8; i++)
                pr[i] = *(const float4*)(kp_s + (ty * 8 + i) * PSTR + n);
#pragma unroll
            for (int nn = 0; nn < 4; nn++) {
                float4 vv = *(const float4*)(v_s + (n + nn) * 64 + tx * 4);
#pragma unroll
                for (int i = 0; i < 8; i++) {
                    float p = (nn == 0) ? pr[i].x : (nn == 1) ? pr[i].y
                            : (nn == 2) ? pr[i].z : pr[i].w;
                    o[i][0] = fmaf(p, vv.x, o[i][0]);
                    o[i][1] = fmaf(p, vv.y, o[i][1]);
                    o[i][2] = fmaf(p, vv.z, o[i][2]);
                    o[i][3] = fmaf(p, vv.w, o[i][3]);
                }
            }
        }
    }

#pragma unroll
    for (int i = 0; i < 8; i++) {
        float inv = 1.f / lrow[i];
        float* op = g_attn + (size_t)(b * SS + q0 + ty * 8 + i) * HH + h * HDD + tx * 4;
        *(float4*)op = make_float4(o[i][0] * inv, o[i][1] * inv, o[i][2] * inv, o[i][3] * inv);
    }
}

// ---------------- launch ----------------
extern "C" void kernel_launch(void* const* d_in, const int* in_sizes, int n_in,
                              void* d_out, int out_size) {
    (void)in_sizes; (void)n_in; (void)out_size;
    const float* hidden = (const float*)d_in[0];
    const float* mask   = (const float*)d_in[1];
    const float* qs = (const float*)d_in[2];
    const float* qd = (const float*)d_in[3];
    const float* ks = (const float*)d_in[4];
    const float* kd = (const float*)d_in[5];
    const float* vs = (const float*)d_in[6];
    const float* vd = (const float*)d_in[7];
    const float* os = (const float*)d_in[8];
    const float* od = (const float*)d_in[9];

    __nv_bfloat16 *a2, *wq2, *wk2, *wv2, *wo2;
    float *q, *k, *v, *attn;
    cudaGetSymbolAddress((void**)&a2,  g_a2);
    cudaGetSymbolAddress((void**)&wq2, g_wq2);
    cudaGetSymbolAddress((void**)&wk2, g_wk2);
    cudaGetSymbolAddress((void**)&wv2, g_wv2);
    cudaGetSymbolAddress((void**)&wo2, g_wo2);
    cudaGetSymbolAddress((void**)&q,   g_q);
    cudaGetSymbolAddress((void**)&k,   g_k);
    cudaGetSymbolAddress((void**)&v,   g_v);
    cudaGetSymbolAddress((void**)&attn, g_attn);

    cudaFuncSetAttribute(attn_kernel, cudaFuncAttributeMaxDynamicSharedMemorySize, ATTN_SMEM);

    // hi/lo splits
    split_kernel<<<MM, 256>>>(hidden, nullptr, a2);         // activations
    split_kernel<<<HH, 256>>>(qs, qd, wq2);
    split_kernel<<<HH, 256>>>(ks, kd, wk2);
    split_kernel<<<HH, 256>>>(vs, vd, wv2);
    split_kernel<<<HH, 256>>>(os, od, wo2);

    // Q,K,V projections fused on grid.z
    tc_gemm<<<dim3(8, 32, 3), 256>>>(a2, wq2, wk2, wv2, q, k, v);

    // attention (fp32)
    attn_kernel<<<dim3(SS / 128, NHH, BB), 256, ATTN_SMEM>>>(mask);

    // O projection: split attn output, then GEMM into d_out
    split_kernel<<<MM, 256>>>(attn, nullptr, a2);
    tc_gemm<<<dim3(8, 32, 1), 256>>>(a2, wo2, wo2, wo2,
                                     (float*)d_out, (float*)d_out, (float*)d_out);
}

// round 5
// speedup vs baseline: 1.7124x; 1.5323x over previous
#include <cuda_runtime.h>
#include <cuda_bf16.h>
#include <cstdint>

// Problem dims
#define BB  2
#define SS  2048
#define HH  1024
#define NHH 16
#define HDD 64
#define MM  (BB*SS)          // 4096 rows

// ---------------- scratch (no cudaMalloc allowed) ----------------
__device__ __nv_bfloat16 g_a2[MM * 2048];        // hi|lo split, [row][0:1024 hi | 1024:2048 lo]
__device__ __nv_bfloat16 g_wq2[HH * 2048];
__device__ __nv_bfloat16 g_wk2[HH * 2048];
__device__ __nv_bfloat16 g_wv2[HH * 2048];
__device__ __nv_bfloat16 g_wo2[HH * 2048];
// per-head split layout: [row][h*128 + (0:64 hi | 64:128 lo)]
__device__ __nv_bfloat16 g_q2[MM * 2048];
__device__ __nv_bfloat16 g_k2[MM * 2048];
__device__ __nv_bfloat16 g_v2[MM * 2048];

// ================= PTX helpers (non-'a' features only) =================
__device__ __forceinline__ uint32_t smem_u32(const void* p) {
    uint32_t a;
    asm("{ .reg .u64 t; cvta.to.shared.u64 t, %1; cvt.u32.u64 %0, t; }" : "=r"(a) : "l"(p));
    return a;
}
__device__ __forceinline__ void cp16(uint32_t dst, const void* src) {
    asm volatile("cp.async.cg.shared.global [%0], [%1], 16;" :: "r"(dst), "l"(src));
}
__device__ __forceinline__ void cp_commit() {
    asm volatile("cp.async.commit_group;" ::: "memory");
}
template<int N> __device__ __forceinline__ void cp_wait() {
    asm volatile("cp.async.wait_group %0;" :: "n"(N) : "memory");
}
__device__ __forceinline__ void ldmat4(uint32_t& r0, uint32_t& r1, uint32_t& r2, uint32_t& r3,
                                       uint32_t addr) {
    asm volatile("ldmatrix.sync.aligned.m8n8.x4.shared.b16 {%0,%1,%2,%3}, [%4];"
                 : "=r"(r0), "=r"(r1), "=r"(r2), "=r"(r3) : "r"(addr));
}
__device__ __forceinline__ void ldmat4t(uint32_t& r0, uint32_t& r1, uint32_t& r2, uint32_t& r3,
                                        uint32_t addr) {
    asm volatile("ldmatrix.sync.aligned.m8n8.x4.trans.shared.b16 {%0,%1,%2,%3}, [%4];"
                 : "=r"(r0), "=r"(r1), "=r"(r2), "=r"(r3) : "r"(addr));
}
__device__ __forceinline__ void mma16816(float* d, uint32_t a0, uint32_t a1, uint32_t a2,
                                         uint32_t a3, uint32_t b0, uint32_t b1) {
    asm volatile("mma.sync.aligned.m16n8k16.row.col.f32.bf16.bf16.f32 "
                 "{%0,%1,%2,%3},{%4,%5,%6,%7},{%8,%9},{%0,%1,%2,%3};"
                 : "+f"(d[0]), "+f"(d[1]), "+f"(d[2]), "+f"(d[3])
                 : "r"(a0), "r"(a1), "r"(a2), "r"(a3), "r"(b0), "r"(b1));
}
__device__ __forceinline__ uint32_t pack_bf2(float x, float y) {
    __nv_bfloat162 t;
    t.x = __float2bfloat16_rn(x);
    t.y = __float2bfloat16_rn(y);
    return *(uint32_t*)&t;
}

// ================= split: out[r][0:1024]=bf16hi(a[+b]), out[r][1024:2048]=bf16lo ======
__global__ void split_kernel(const float* __restrict__ a, const float* __restrict__ b,
                             __nv_bfloat16* __restrict__ out) {
    int i = blockIdx.x * 256 + threadIdx.x;
    int r = i >> 8;
    int c4 = (i & 255) << 2;
    float4 x = ((const float4*)a)[i];
    if (b) {
        float4 y = ((const float4*)b)[i];
        x.x += y.x; x.y += y.y; x.z += y.z; x.w += y.w;
    }
    float vf[4] = {x.x, x.y, x.z, x.w};
    __nv_bfloat16 h[4], l[4];
#pragma unroll
    for (int j = 0; j < 4; j++) {
        h[j] = __float2bfloat16_rn(vf[j]);
        l[j] = __float2bfloat16_rn(vf[j] - __bfloat162float(h[j]));
    }
    __nv_bfloat16* o = out + (size_t)r * 2048 + c4;
    ((__nv_bfloat162*)o)[0] = __halves2bfloat162(h[0], h[1]);
    ((__nv_bfloat162*)o)[1] = __halves2bfloat162(h[2], h[3]);
    ((__nv_bfloat162*)(o + 1024))[0] = __halves2bfloat162(l[0], l[1]);
    ((__nv_bfloat162*)(o + 1024))[1] = __halves2bfloat162(l[2], l[3]);
}

// ================= HMMA split-bf16 GEMM (3-stage cp.async pipeline) =================
// C[4096,1024] = A @ W^T, hi/lo split (3 terms, K-concat 3072). CTA 128x128, 8 warps,
// warp 32x64, K-chunk 32, 3 stages, ONE barrier per chunk.
// EP=0: fp32 C.  EP=1: per-head split bf16 (g_q2 layout).
#define ROWB 80
#define TILEB (128 * ROWB)
#define STAGEB (2 * TILEB)               // 20480
#define NCH 96

template<int EP>
__global__ __launch_bounds__(256, 1)
void tc_gemm(const __nv_bfloat16* __restrict__ A2,
             const __nv_bfloat16* __restrict__ W2q,
             const __nv_bfloat16* __restrict__ W2k,
             const __nv_bfloat16* __restrict__ W2v,
             void* __restrict__ O0, void* __restrict__ O1, void* __restrict__ O2) {
    extern __shared__ __align__(128) char smbuf[];
    const uint32_t sbase = smem_u32(smbuf);

    const __nv_bfloat16* W2 = (blockIdx.z == 0) ? W2q : (blockIdx.z == 1) ? W2k : W2v;
    void* OUT = (blockIdx.z == 0) ? O0 : (blockIdx.z == 1) ? O1 : O2;

    const int tid = threadIdx.x;
    const int wid = tid >> 5;
    const int lane = tid & 31;
    const int m0 = blockIdx.y * 128;
    const int n0 = blockIdx.x * 128;

    const int isA = (tid < 128);
    const int lrow128 = isA ? tid : (tid - 128);
    const __nv_bfloat16* gbase = isA ? (A2 + (size_t)(m0 + lrow128) * 2048)
                                     : (W2 + (size_t)(n0 + lrow128) * 2048);
    const uint32_t sdst0 = sbase + (isA ? 0 : TILEB) + lrow128 * ROWB;
    const int offT[3] = { 0, isA ? 0 : 1024, isA ? 1024 : 0 };

    const int mi = lane >> 3, rr = lane & 7;
    const int lmrow = (mi & 1) * 8 + rr;
    const int lmunit = (mi >> 1);
    const int wm = wid >> 1;
    const int wn = wid & 1;

    float acc[2][8][4];
#pragma unroll
    for (int am = 0; am < 2; am++)
#pragma unroll
        for (int bn = 0; bn < 8; bn++)
#pragma unroll
            for (int j = 0; j < 4; j++) acc[am][bn][j] = 0.f;

    // prologue: chunks 0,1 -> stages 0,1
#pragma unroll
    for (int p = 0; p < 2; p++) {
        const __nv_bfloat16* src = gbase + offT[0] + p * 32;
        const uint32_t d = sdst0 + p * STAGEB;
#pragma unroll
        for (int q = 0; q < 4; q++) cp16(d + q * 16, src + q * 8);
        cp_commit();
    }

    for (int c = 0; c < NCH; ++c) {
        if (c + 1 < NCH) cp_wait<1>(); else cp_wait<0>();
        __syncthreads();

        if (c + 2 < NCH) {
            const int cn = c + 2;
            const int t = cn >> 5, kc = cn & 31;
            const __nv_bfloat16* src = gbase + offT[t] + kc * 32;
            const uint32_t d = sdst0 + (uint32_t)(cn % 3) * STAGEB;
#pragma unroll
            for (int q = 0; q < 4; q++) cp16(d + q * 16, src + q * 8);
            cp_commit();
        }

        const uint32_t sA = sbase + (uint32_t)(c % 3) * STAGEB;
        const uint32_t sB = sA + TILEB;
#pragma unroll
        for (int kb = 0; kb < 2; kb++) {
            uint32_t a[2][4];
#pragma unroll
            for (int am = 0; am < 2; am++)
                ldmat4(a[am][0], a[am][1], a[am][2], a[am][3],
                       sA + (wm * 32 + am * 16 + lmrow) * ROWB + (kb * 2 + lmunit) * 16);
#pragma unroll
            for (int bb = 0; bb < 4; bb++) {
                uint32_t r0, r1, r2, r3;
                ldmat4(r0, r1, r2, r3,
                       sB + (wn * 64 + bb * 16 + lmrow) * ROWB + (kb * 2 + lmunit) * 16);
#pragma unroll
                for (int am = 0; am < 2; am++) {
                    mma16816(acc[am][bb * 2],     a[am][0], a[am][1], a[am][2], a[am][3], r0, r2);
                    mma16816(acc[am][bb * 2 + 1], a[am][0], a[am][1], a[am][2], a[am][3], r1, r3);
                }
            }
        }
    }

    const int g = lane >> 2, it = lane & 3;
#pragma unroll
    for (int am = 0; am < 2; am++) {
        const int row0 = m0 + wm * 32 + am * 16 + g;
#pragma unroll
        for (int bn = 0; bn < 8; bn++) {
            const int col = n0 + wn * 64 + bn * 8 + it * 2;
            if (EP == 0) {
                float* p0 = (float*)OUT + (size_t)row0 * 1024 + col;
                float* p1 = p0 + 8 * 1024;
                *(float2*)p0 = make_float2(acc[am][bn][0], acc[am][bn][1]);
                *(float2*)p1 = make_float2(acc[am][bn][2], acc[am][bn][3]);
            } else {
                const int h = col >> 6, d = col & 63;
#pragma unroll
                for (int half = 0; half < 2; half++) {
                    float v0 = acc[am][bn][half * 2], v1 = acc[am][bn][half * 2 + 1];
                    __nv_bfloat16 h0 = __float2bfloat16_rn(v0);
                    __nv_bfloat16 h1 = __float2bfloat16_rn(v1);
                    __nv_bfloat162 hi2; hi2.x = h0; hi2.y = h1;
                    __nv_bfloat162 lo2;
                    lo2.x = __float2bfloat16_rn(v0 - __bfloat162float(h0));
                    lo2.y = __float2bfloat16_rn(v1 - __bfloat162float(h1));
                    __nv_bfloat16* op = (__nv_bfloat16*)OUT
                        + (size_t)(row0 + half * 8) * 2048 + h * 128 + d;
                    *(__nv_bfloat162*)op = hi2;
                    *(__nv_bfloat162*)(op + 64) = lo2;
                }
            }
        }
    }
}

// ================= HMMA flash attention (split bf16, 3-term) =================
// CTA: 128 q-rows x one (b,h). 8 warps x 16 full-width rows. kt tiles of 128.
// smem rows padded to 272B (17 16B-units; 17r+u mod 8 bijective -> conflict-free).
#define TROW 272
#define ATILE (128 * TROW)               // 34816
#define ATTN_SMEM (5 * ATILE)            // Q + 2x(K,V) = 174080

__global__ __launch_bounds__(256, 1)
void attn_tc(const float* __restrict__ mask,
             const __nv_bfloat16* __restrict__ Q2,
             const __nv_bfloat16* __restrict__ K2,
             const __nv_bfloat16* __restrict__ V2,
             __nv_bfloat16* __restrict__ Aout) {
    extern __shared__ __align__(128) char smc[];
    const uint32_t sq = smem_u32(smc);

    const int tid = threadIdx.x;
    const int wid = tid >> 5;
    const int lane = tid & 31;
    const int g = lane >> 2, it = lane & 3;
    const int lmrow = ((lane >> 3) & 1) * 8 + (lane & 7);
    const int lmunit = lane >> 4;

    const int b = blockIdx.z, h = blockIdx.y;
    const int q0 = blockIdx.x * 128;
    const size_t brow = (size_t)b * SS;

    // load Q tile (8 cp16/thread)
#pragma unroll
    for (int i = 0; i < 8; i++) {
        int idx = tid + i * 256;
        int u = idx & 15, r = idx >> 4;
        cp16(sq + r * TROW + u * 16, Q2 + (brow + q0 + r) * 2048 + h * 128 + u * 8);
    }
    cp_commit();

    // prefetch KV tile 0 -> buf 0
#pragma unroll
    for (int i = 0; i < 8; i++) {
        int idx = tid + i * 256;
        int u = idx & 15, r = idx >> 4;
        cp16(sq + ATILE + r * TROW + u * 16, K2 + (brow + r) * 2048 + h * 128 + u * 8);
        cp16(sq + 2 * ATILE + r * TROW + u * 16, V2 + (brow + r) * 2048 + h * 128 + u * 8);
    }
    cp_commit();

    float o[8][4];
#pragma unroll
    for (int dn = 0; dn < 8; dn++)
#pragma unroll
        for (int j = 0; j < 4; j++) o[dn][j] = 0.f;
    float mst0 = -INFINITY, mst1 = -INFINITY, l0 = 0.f, l1 = 0.f;

    const float* mrow0 = mask + ((size_t)b * SS + q0 + wid * 16 + g) * SS;
    const float* mrow1 = mrow0 + 8 * SS;

    for (int kt = 0; kt < 16; kt++) {
        const int cur = kt & 1;
        cp_wait<0>();
        __syncthreads();

        if (kt + 1 < 16) {
            const uint32_t kb = sq + (uint32_t)(1 + 2 * (cur ^ 1)) * ATILE;
#pragma unroll
            for (int i = 0; i < 8; i++) {
                int idx = tid + i * 256;
                int u = idx & 15, r = idx >> 4;
                const size_t grow = brow + (size_t)(kt + 1) * 128 + r;
                cp16(kb + r * TROW + u * 16, K2 + grow * 2048 + h * 128 + u * 8);
                cp16(kb + ATILE + r * TROW + u * 16, V2 + grow * 2048 + h * 128 + u * 8);
            }
            cp_commit();
        }

        const uint32_t sk = sq + (uint32_t)(1 + 2 * cur) * ATILE;
        const uint32_t sv = sk + ATILE;

        // ---- S = 3-term QK^T ----
        float s[16][4];
#pragma unroll
        for (int nb = 0; nb < 16; nb++)
#pragma unroll
            for (int j = 0; j < 4; j++) s[nb][j] = 0.f;

        const int aU[12] = {0,2,4,6, 0,2,4,6, 8,10,12,14};
        const int bU[12] = {0,2,4,6, 8,10,12,14, 0,2,4,6};
#pragma unroll
        for (int st = 0; st < 12; st++) {
            uint32_t a0, a1, a2, a3;
            ldmat4(a0, a1, a2, a3,
                   sq + (wid * 16 + lmrow) * TROW + (aU[st] + lmunit) * 16);
#pragma unroll
            for (int nb16 = 0; nb16 < 8; nb16++) {
                uint32_t r0, r1, r2, r3;
                ldmat4(r0, r1, r2, r3,
                       sk + (nb16 * 16 + lmrow) * TROW + (bU[st] + lmunit) * 16);
                mma16816(s[nb16 * 2],     a0, a1, a2, a3, r0, r2);
                mma16816(s[nb16 * 2 + 1], a0, a1, a2, a3, r1, r3);
            }
        }

        // ---- scale + mask ----
        float mx0 = -INFINITY, mx1 = -INFINITY;
#pragma unroll
        for (int nb = 0; nb < 16; nb++) {
            const int col = kt * 128 + nb * 8 + it * 2;
            float2 m0 = *(const float2*)(mrow0 + col);
            float2 m1 = *(const float2*)(mrow1 + col);
            s[nb][0] = fmaf(s[nb][0], 0.125f, m0.x);
            s[nb][1] = fmaf(s[nb][1], 0.125f, m0.y);
            s[nb][2] = fmaf(s[nb][2], 0.125f, m1.x);
            s[nb][3] = fmaf(s[nb][3], 0.125f, m1.y);
            mx0 = fmaxf(mx0, fmaxf(s[nb][0], s[nb][1]));
            mx1 = fmaxf(mx1, fmaxf(s[nb][2], s[nb][3]));
        }
        mx0 = fmaxf(mx0, __shfl_xor_sync(0xffffffffu, mx0, 1));
        mx0 = fmaxf(mx0, __shfl_xor_sync(0xffffffffu, mx0, 2));
        mx1 = fmaxf(mx1, __shfl_xor_sync(0xffffffffu, mx1, 1));
        mx1 = fmaxf(mx1, __shfl_xor_sync(0xffffffffu, mx1, 2));

        const float nm0 = fmaxf(mst0, mx0), nm1 = fmaxf(mst1, mx1);
        const float corr0 = __expf(mst0 - nm0), corr1 = __expf(mst1 - nm1);
        mst0 = nm0; mst1 = nm1;

        // ---- exp + P hi/lo fragments (register-local) ----
        uint32_t phi[32], plo[32];
        float sum0 = 0.f, sum1 = 0.f;
#pragma unroll
        for (int nb = 0; nb < 16; nb++) {
            float p0 = __expf(s[nb][0] - nm0);
            float p1 = __expf(s[nb][1] - nm0);
            float p2 = __expf(s[nb][2] - nm1);
            float p3 = __expf(s[nb][3] - nm1);
            sum0 += p0 + p1; sum1 += p2 + p3;
            float h0 = __bfloat162float(__float2bfloat16_rn(p0));
            float h1 = __bfloat162float(__float2bfloat16_rn(p1));
            float h2 = __bfloat162float(__float2bfloat16_rn(p2));
            float h3 = __bfloat162float(__float2bfloat16_rn(p3));
            const int kk = nb >> 1;
            const int base = kk * 4 + (nb & 1) * 2;
            phi[base]     = pack_bf2(h0, h1);
            phi[base + 1] = pack_bf2(h2, h3);
            plo[base]     = pack_bf2(p0 - h0, p1 - h1);
            plo[base + 1] = pack_bf2(p2 - h2, p3 - h3);
        }
        sum0 += __shfl_xor_sync(0xffffffffu, sum0, 1);
        sum0 += __shfl_xor_sync(0xffffffffu, sum0, 2);
        sum1 += __shfl_xor_sync(0xffffffffu, sum1, 1);
        sum1 += __shfl_xor_sync(0xffffffffu, sum1, 2);
        l0 = l0 * corr0 + sum0;
        l1 = l1 * corr1 + sum1;
#pragma unroll
        for (int dn = 0; dn < 8; dn++) {
            o[dn][0] *= corr0; o[dn][1] *= corr0;
            o[dn][2] *= corr1; o[dn][3] *= corr1;
        }

        // ---- O += 3-term P V  (B frags via ldmatrix.trans of V[s][d]) ----
#pragma unroll
        for (int t = 0; t < 3; t++) {
            const uint32_t* af = (t == 2) ? plo : phi;
            const int duBase = (t == 1) ? 8 : 0;
#pragma unroll
            for (int kk = 0; kk < 8; kk++) {
                const uint32_t* a = af + kk * 4;
#pragma unroll
                for (int dn16 = 0; dn16 < 4; dn16++) {
                    uint32_t r0, r1, r2, r3;
                    ldmat4t(r0, r1, r2, r3,
                            sv + (kk * 16 + lmrow) * TROW + (duBase + dn16 * 2 + lmunit) * 16);
                    mma16816(o[dn16 * 2],     a[0], a[1], a[2], a[3], r0, r1);
                    mma16816(o[dn16 * 2 + 1], a[0], a[1], a[2], a[3], r2, r3);
                }
            }
        }
    }

    // ---- epilogue: normalize, split hi/lo, write A2-format ----
    const float inv0 = 1.f / l0, inv1 = 1.f / l1;
    const size_t row0 = brow + q0 + wid * 16 + g;
#pragma unroll
    for (int dn = 0; dn < 8; dn++) {
        const int col = h * 64 + dn * 8 + it * 2;
        float v0 = o[dn][0] * inv0, v1 = o[dn][1] * inv0;
        float v2 = o[dn][2] * inv1, v3 = o[dn][3] * inv1;
        __nv_bfloat16 h0 = __float2bfloat16_rn(v0), h1 = __float2bfloat16_rn(v1);
        __nv_bfloat16 h2 = __float2bfloat16_rn(v2), h3 = __float2bfloat16_rn(v3);
        __nv_bfloat162 hi01; hi01.x = h0; hi01.y = h1;
        __nv_bfloat162 hi23; hi23.x = h2; hi23.y = h3;
        __nv_bfloat162 lo01, lo23;
        lo01.x = __float2bfloat16_rn(v0 - __bfloat162float(h0));
        lo01.y = __float2bfloat16_rn(v1 - __bfloat162float(h1));
        lo23.x = __float2bfloat16_rn(v2 - __bfloat162float(h2));
        lo23.y = __float2bfloat16_rn(v3 - __bfloat162float(h3));
        __nv_bfloat16* p0 = Aout + row0 * 2048 + col;
        __nv_bfloat16* p1 = Aout + (row0 + 8) * 2048 + col;
        *(__nv_bfloat162*)p0 = hi01;
        *(__nv_bfloat162*)(p0 + 1024) = lo01;
        *(__nv_bfloat162*)p1 = hi23;
        *(__nv_bfloat162*)(p1 + 1024) = lo23;
    }
}

// ---------------- launch ----------------
extern "C" void kernel_launch(void* const* d_in, const int* in_sizes, int n_in,
                              void* d_out, int out_size) {
    (void)in_sizes; (void)n_in; (void)out_size;
    const float* hidden = (const float*)d_in[0];
    const float* mask   = (const float*)d_in[1];
    const float* qs = (const float*)d_in[2];
    const float* qd = (const float*)d_in[3];
    const float* ks = (const float*)d_in[4];
    const float* kd = (const float*)d_in[5];
    const float* vs = (const float*)d_in[6];
    const float* vd = (const float*)d_in[7];
    const float* os = (const float*)d_in[8];
    const float* od = (const float*)d_in[9];

    __nv_bfloat16 *a2, *wq2, *wk2, *wv2, *wo2, *q2, *k2, *v2;
    cudaGetSymbolAddress((void**)&a2,  g_a2);
    cudaGetSymbolAddress((void**)&wq2, g_wq2);
    cudaGetSymbolAddress((void**)&wk2, g_wk2);
    cudaGetSymbolAddress((void**)&wv2, g_wv2);
    cudaGetSymbolAddress((void**)&wo2, g_wo2);
    cudaGetSymbolAddress((void**)&q2,  g_q2);
    cudaGetSymbolAddress((void**)&k2,  g_k2);
    cudaGetSymbolAddress((void**)&v2,  g_v2);

    static int configured = -1;
    cudaFuncSetAttribute(tc_gemm<0>, cudaFuncAttributeMaxDynamicSharedMemorySize, 3 * STAGEB);
    cudaFuncSetAttribute(tc_gemm<1>, cudaFuncAttributeMaxDynamicSharedMemorySize, 3 * STAGEB);
    cudaFuncSetAttribute(attn_tc, cudaFuncAttributeMaxDynamicSharedMemorySize, ATTN_SMEM);
    (void)configured;

    // hi/lo splits
    split_kernel<<<MM, 256>>>(hidden, nullptr, a2);
    split_kernel<<<HH, 256>>>(qs, qd, wq2);
    split_kernel<<<HH, 256>>>(ks, kd, wk2);
    split_kernel<<<HH, 256>>>(vs, vd, wv2);
    split_kernel<<<HH, 256>>>(os, od, wo2);

    // Q,K,V projections -> per-head split bf16
    tc_gemm<1><<<dim3(8, 32, 3), 256, 3 * STAGEB>>>(a2, wq2, wk2, wv2, q2, k2, v2);

    // attention -> writes A2-format split directly into g_a2 (reused)
    attn_tc<<<dim3(SS / 128, NHH, BB), 256, ATTN_SMEM>>>(mask, q2, k2, v2, a2);

    // O projection -> fp32 d_out
    tc_gemm<0><<<dim3(8, 32, 1), 256, 3 * STAGEB>>>(a2, wo2, wo2, wo2,
                                                    d_out, d_out, d_out);
}

// round 6
// speedup vs baseline: 1.9252x; 1.1242x over previous
#include <cuda_runtime.h>
#include <cuda_bf16.h>
#include <cstdint>

// Problem dims
#define BB  2
#define SS  2048
#define HH  1024
#define NHH 16
#define HDD 64
#define MM  (BB*SS)          // 4096 rows

// ---------------- scratch (no cudaMalloc allowed) ----------------
__device__ __nv_bfloat16 g_a2[MM * 2048];        // hi|lo split, [row][0:1024 hi | 1024:2048 lo]
__device__ __nv_bfloat16 g_wq2[HH * 2048];
__device__ __nv_bfloat16 g_wk2[HH * 2048];
__device__ __nv_bfloat16 g_wv2[HH * 2048];
__device__ __nv_bfloat16 g_wo2[HH * 2048];
// per-head split layout: [row][h*128 + (0:64 hi | 64:128 lo)]
__device__ __nv_bfloat16 g_q2[MM * 2048];
__device__ __nv_bfloat16 g_k2[MM * 2048];
__device__ __nv_bfloat16 g_v2[MM * 2048];

// ================= PTX helpers (non-'a' features only) =================
__device__ __forceinline__ uint32_t smem_u32(const void* p) {
    uint32_t a;
    asm("{ .reg .u64 t; cvta.to.shared.u64 t, %1; cvt.u32.u64 %0, t; }" : "=r"(a) : "l"(p));
    return a;
}
__device__ __forceinline__ void cp16(uint32_t dst, const void* src) {
    asm volatile("cp.async.cg.shared.global [%0], [%1], 16;" :: "r"(dst), "l"(src));
}
__device__ __forceinline__ void cp_commit() {
    asm volatile("cp.async.commit_group;" ::: "memory");
}
template<int N> __device__ __forceinline__ void cp_wait() {
    asm volatile("cp.async.wait_group %0;" :: "n"(N) : "memory");
}
__device__ __forceinline__ void ldmat4(uint32_t& r0, uint32_t& r1, uint32_t& r2, uint32_t& r3,
                                       uint32_t addr) {
    asm volatile("ldmatrix.sync.aligned.m8n8.x4.shared.b16 {%0,%1,%2,%3}, [%4];"
                 : "=r"(r0), "=r"(r1), "=r"(r2), "=r"(r3) : "r"(addr));
}
__device__ __forceinline__ void ldmat4t(uint32_t& r0, uint32_t& r1, uint32_t& r2, uint32_t& r3,
                                        uint32_t addr) {
    asm volatile("ldmatrix.sync.aligned.m8n8.x4.trans.shared.b16 {%0,%1,%2,%3}, [%4];"
                 : "=r"(r0), "=r"(r1), "=r"(r2), "=r"(r3) : "r"(addr));
}
__device__ __forceinline__ void mma16816(float* d, uint32_t a0, uint32_t a1, uint32_t a2,
                                         uint32_t a3, uint32_t b0, uint32_t b1) {
    asm volatile("mma.sync.aligned.m16n8k16.row.col.f32.bf16.bf16.f32 "
                 "{%0,%1,%2,%3},{%4,%5,%6,%7},{%8,%9},{%0,%1,%2,%3};"
                 : "+f"(d[0]), "+f"(d[1]), "+f"(d[2]), "+f"(d[3])
                 : "r"(a0), "r"(a1), "r"(a2), "r"(a3), "r"(b0), "r"(b1));
}
__device__ __forceinline__ uint32_t pack_bf2(float x, float y) {
    __nv_bfloat162 t;
    t.x = __float2bfloat16_rn(x);
    t.y = __float2bfloat16_rn(y);
    return *(uint32_t*)&t;
}

// ================= splits =================
__global__ void split_kernel(const float* __restrict__ a, const float* __restrict__ b,
                             __nv_bfloat16* __restrict__ out) {
    int i = blockIdx.x * 256 + threadIdx.x;
    int r = i >> 8;
    int c4 = (i & 255) << 2;
    float4 x = ((const float4*)a)[i];
    if (b) {
        float4 y = ((const float4*)b)[i];
        x.x += y.x; x.y += y.y; x.z += y.z; x.w += y.w;
    }
    float vf[4] = {x.x, x.y, x.z, x.w};
    __nv_bfloat16 h[4], l[4];
#pragma unroll
    for (int j = 0; j < 4; j++) {
        h[j] = __float2bfloat16_rn(vf[j]);
        l[j] = __float2bfloat16_rn(vf[j] - __bfloat162float(h[j]));
    }
    __nv_bfloat16* o = out + (size_t)r * 2048 + c4;
    ((__nv_bfloat162*)o)[0] = __halves2bfloat162(h[0], h[1]);
    ((__nv_bfloat162*)o)[1] = __halves2bfloat162(h[2], h[3]);
    ((__nv_bfloat162*)(o + 1024))[0] = __halves2bfloat162(l[0], l[1]);
    ((__nv_bfloat162*)(o + 1024))[1] = __halves2bfloat162(l[2], l[3]);
}

// fused 4-weight split: grid (1024, 4)
__global__ void wsplit4_kernel(const float* __restrict__ s0, const float* __restrict__ d0,
                               const float* __restrict__ s1, const float* __restrict__ d1,
                               const float* __restrict__ s2, const float* __restrict__ d2,
                               const float* __restrict__ s3, const float* __restrict__ d3,
                               __nv_bfloat16* __restrict__ o0, __nv_bfloat16* __restrict__ o1,
                               __nv_bfloat16* __restrict__ o2, __nv_bfloat16* __restrict__ o3) {
    const int w = blockIdx.y;
    const float* a = (w == 0) ? s0 : (w == 1) ? s1 : (w == 2) ? s2 : s3;
    const float* b = (w == 0) ? d0 : (w == 1) ? d1 : (w == 2) ? d2 : d3;
    __nv_bfloat16* out = (w == 0) ? o0 : (w == 1) ? o1 : (w == 2) ? o2 : o3;

    int i = blockIdx.x * 256 + threadIdx.x;
    int r = i >> 8;
    int c4 = (i & 255) << 2;
    float4 x = ((const float4*)a)[i];
    float4 y = ((const float4*)b)[i];
    x.x += y.x; x.y += y.y; x.z += y.z; x.w += y.w;
    float vf[4] = {x.x, x.y, x.z, x.w};
    __nv_bfloat16 h[4], l[4];
#pragma unroll
    for (int j = 0; j < 4; j++) {
        h[j] = __float2bfloat16_rn(vf[j]);
        l[j] = __float2bfloat16_rn(vf[j] - __bfloat162float(h[j]));
    }
    __nv_bfloat16* o = out + (size_t)r * 2048 + c4;
    ((__nv_bfloat162*)o)[0] = __halves2bfloat162(h[0], h[1]);
    ((__nv_bfloat162*)o)[1] = __halves2bfloat162(h[2], h[3]);
    ((__nv_bfloat162*)(o + 1024))[0] = __halves2bfloat162(l[0], l[1]);
    ((__nv_bfloat162*)(o + 1024))[1] = __halves2bfloat162(l[2], l[3]);
}

// ================= HMMA split-bf16 GEMM (3-stage, occupancy 2) =================
#define ROWB 80
#define TILEB (128 * ROWB)
#define STAGEB (2 * TILEB)               // 20480
#define NCH 96

template<int EP>
__global__ __launch_bounds__(256, 2)
void tc_gemm(const __nv_bfloat16* __restrict__ A2,
             const __nv_bfloat16* __restrict__ W2q,
             const __nv_bfloat16* __restrict__ W2k,
             const __nv_bfloat16* __restrict__ W2v,
             void* __restrict__ O0, void* __restrict__ O1, void* __restrict__ O2) {
    extern __shared__ __align__(128) char smbuf[];
    const uint32_t sbase = smem_u32(smbuf);

    const __nv_bfloat16* W2 = (blockIdx.z == 0) ? W2q : (blockIdx.z == 1) ? W2k : W2v;
    void* OUT = (blockIdx.z == 0) ? O0 : (blockIdx.z == 1) ? O1 : O2;

    const int tid = threadIdx.x;
    const int wid = tid >> 5;
    const int lane = tid & 31;
    const int m0 = blockIdx.y * 128;
    const int n0 = blockIdx.x * 128;

    const int isA = (tid < 128);
    const int lrow128 = isA ? tid : (tid - 128);
    const __nv_bfloat16* gbase = isA ? (A2 + (size_t)(m0 + lrow128) * 2048)
                                     : (W2 + (size_t)(n0 + lrow128) * 2048);
    const uint32_t sdst0 = sbase + (isA ? 0 : TILEB) + lrow128 * ROWB;
    const int offT[3] = { 0, isA ? 0 : 1024, isA ? 1024 : 0 };

    const int mi = lane >> 3, rr = lane & 7;
    const int lmrow = (mi & 1) * 8 + rr;
    const int lmunit = (mi >> 1);
    const int wm = wid >> 1;
    const int wn = wid & 1;

    float acc[2][8][4];
#pragma unroll
    for (int am = 0; am < 2; am++)
#pragma unroll
        for (int bn = 0; bn < 8; bn++)
#pragma unroll
            for (int j = 0; j < 4; j++) acc[am][bn][j] = 0.f;

#pragma unroll
    for (int p = 0; p < 2; p++) {
        const __nv_bfloat16* src = gbase + offT[0] + p * 32;
        const uint32_t d = sdst0 + p * STAGEB;
#pragma unroll
        for (int q = 0; q < 4; q++) cp16(d + q * 16, src + q * 8);
        cp_commit();
    }

    for (int c = 0; c < NCH; ++c) {
        if (c + 1 < NCH) cp_wait<1>(); else cp_wait<0>();
        __syncthreads();

        if (c + 2 < NCH) {
            const int cn = c + 2;
            const int t = cn >> 5, kc = cn & 31;
            const __nv_bfloat16* src = gbase + offT[t] + kc * 32;
            const uint32_t d = sdst0 + (uint32_t)(cn % 3) * STAGEB;
#pragma unroll
            for (int q = 0; q < 4; q++) cp16(d + q * 16, src + q * 8);
            cp_commit();
        }

        const uint32_t sA = sbase + (uint32_t)(c % 3) * STAGEB;
        const uint32_t sB = sA + TILEB;
#pragma unroll
        for (int kb = 0; kb < 2; kb++) {
            uint32_t a[2][4];
#pragma unroll
            for (int am = 0; am < 2; am++)
                ldmat4(a[am][0], a[am][1], a[am][2], a[am][3],
                       sA + (wm * 32 + am * 16 + lmrow) * ROWB + (kb * 2 + lmunit) * 16);
#pragma unroll
            for (int bb = 0; bb < 4; bb++) {
                uint32_t r0, r1, r2, r3;
                ldmat4(r0, r1, r2, r3,
                       sB + (wn * 64 + bb * 16 + lmrow) * ROWB + (kb * 2 + lmunit) * 16);
#pragma unroll
                for (int am = 0; am < 2; am++) {
                    mma16816(acc[am][bb * 2],     a[am][0], a[am][1], a[am][2], a[am][3], r0, r2);
                    mma16816(acc[am][bb * 2 + 1], a[am][0], a[am][1], a[am][2], a[am][3], r1, r3);
                }
            }
        }
    }

    const int g = lane >> 2, it = lane & 3;
#pragma unroll
    for (int am = 0; am < 2; am++) {
        const int row0 = m0 + wm * 32 + am * 16 + g;
#pragma unroll
        for (int bn = 0; bn < 8; bn++) {
            const int col = n0 + wn * 64 + bn * 8 + it * 2;
            if (EP == 0) {
                float* p0 = (float*)OUT + (size_t)row0 * 1024 + col;
                float* p1 = p0 + 8 * 1024;
                *(float2*)p0 = make_float2(acc[am][bn][0], acc[am][bn][1]);
                *(float2*)p1 = make_float2(acc[am][bn][2], acc[am][bn][3]);
            } else {
                const int h = col >> 6, d = col & 63;
#pragma unroll
                for (int half = 0; half < 2; half++) {
                    float v0 = acc[am][bn][half * 2], v1 = acc[am][bn][half * 2 + 1];
                    __nv_bfloat16 h0 = __float2bfloat16_rn(v0);
                    __nv_bfloat16 h1 = __float2bfloat16_rn(v1);
                    __nv_bfloat162 hi2; hi2.x = h0; hi2.y = h1;
                    __nv_bfloat162 lo2;
                    lo2.x = __float2bfloat16_rn(v0 - __bfloat162float(h0));
                    lo2.y = __float2bfloat16_rn(v1 - __bfloat162float(h1));
                    __nv_bfloat16* op = (__nv_bfloat16*)OUT
                        + (size_t)(row0 + half * 8) * 2048 + h * 128 + d;
                    *(__nv_bfloat162*)op = hi2;
                    *(__nv_bfloat162*)(op + 64) = lo2;
                }
            }
        }
    }
}

// ================= HMMA flash attention (split bf16, fragment-deduped) =================
#define TROW 272
#define ATILE (128 * TROW)               // 34816
#define ATTN_SMEM (5 * ATILE)            // Q + 2x(K,V) = 174080

__global__ __launch_bounds__(256, 1)
void attn_tc(const float* __restrict__ mask,
             const __nv_bfloat16* __restrict__ Q2,
             const __nv_bfloat16* __restrict__ K2,
             const __nv_bfloat16* __restrict__ V2,
             __nv_bfloat16* __restrict__ Aout) {
    extern __shared__ __align__(128) char smc[];
    const uint32_t sq = smem_u32(smc);

    const int tid = threadIdx.x;
    const int wid = tid >> 5;
    const int lane = tid & 31;
    const int g = lane >> 2, it = lane & 3;
    const int lmrow = ((lane >> 3) & 1) * 8 + (lane & 7);
    const int lmunit = lane >> 4;

    const int b = blockIdx.z, h = blockIdx.y;
    const int q0 = blockIdx.x * 128;
    const size_t brow = (size_t)b * SS;

#pragma unroll
    for (int i = 0; i < 8; i++) {
        int idx = tid + i * 256;
        int u = idx & 15, r = idx >> 4;
        cp16(sq + r * TROW + u * 16, Q2 + (brow + q0 + r) * 2048 + h * 128 + u * 8);
    }
    cp_commit();

#pragma unroll
    for (int i = 0; i < 8; i++) {
        int idx = tid + i * 256;
        int u = idx & 15, r = idx >> 4;
        cp16(sq + ATILE + r * TROW + u * 16, K2 + (brow + r) * 2048 + h * 128 + u * 8);
        cp16(sq + 2 * ATILE + r * TROW + u * 16, V2 + (brow + r) * 2048 + h * 128 + u * 8);
    }
    cp_commit();

    float o[8][4];
#pragma unroll
    for (int dn = 0; dn < 8; dn++)
#pragma unroll
        for (int j = 0; j < 4; j++) o[dn][j] = 0.f;
    float mst0 = -INFINITY, mst1 = -INFINITY, l0 = 0.f, l1 = 0.f;

    const float* mrow0 = mask + ((size_t)b * SS + q0 + wid * 16 + g) * SS;
    const float* mrow1 = mrow0 + 8 * SS;

    for (int kt = 0; kt < 16; kt++) {
        const int cur = kt & 1;
        cp_wait<0>();
        __syncthreads();

        if (kt + 1 < 16) {
            const uint32_t kb = sq + (uint32_t)(1 + 2 * (cur ^ 1)) * ATILE;
#pragma unroll
            for (int i = 0; i < 8; i++) {
                int idx = tid + i * 256;
                int u = idx & 15, r = idx >> 4;
                const size_t grow = brow + (size_t)(kt + 1) * 128 + r;
                cp16(kb + r * TROW + u * 16, K2 + grow * 2048 + h * 128 + u * 8);
                cp16(kb + ATILE + r * TROW + u * 16, V2 + grow * 2048 + h * 128 + u * 8);
            }
            cp_commit();
        }

        const uint32_t sk = sq + (uint32_t)(1 + 2 * cur) * ATILE;
        const uint32_t sv = sk + ATILE;

        // ---- S = 3-term QK^T (A frags deduped; K-hi frags shared by hi*hi & lo*hi) ----
        float s[16][4];
#pragma unroll
        for (int nb = 0; nb < 16; nb++)
#pragma unroll
            for (int j = 0; j < 4; j++) s[nb][j] = 0.f;

        uint32_t afr[8][4];              // k16 frags: 0-3 = Q hi, 4-7 = Q lo
#pragma unroll
        for (int u4 = 0; u4 < 4; u4++) {
            ldmat4(afr[u4][0], afr[u4][1], afr[u4][2], afr[u4][3],
                   sq + (wid * 16 + lmrow) * TROW + (u4 * 2 + lmunit) * 16);
            ldmat4(afr[4 + u4][0], afr[4 + u4][1], afr[4 + u4][2], afr[4 + u4][3],
                   sq + (wid * 16 + lmrow) * TROW + (8 + u4 * 2 + lmunit) * 16);
        }
        // K hi: Qhi*Khi + Qlo*Khi
#pragma unroll
        for (int u4 = 0; u4 < 4; u4++) {
#pragma unroll
            for (int nb16 = 0; nb16 < 8; nb16++) {
                uint32_t r0, r1, r2, r3;
                ldmat4(r0, r1, r2, r3,
                       sk + (nb16 * 16 + lmrow) * TROW + (u4 * 2 + lmunit) * 16);
                mma16816(s[nb16 * 2],     afr[u4][0], afr[u4][1], afr[u4][2], afr[u4][3], r0, r2);
                mma16816(s[nb16 * 2 + 1], afr[u4][0], afr[u4][1], afr[u4][2], afr[u4][3], r1, r3);
                mma16816(s[nb16 * 2],     afr[4+u4][0], afr[4+u4][1], afr[4+u4][2], afr[4+u4][3], r0, r2);
                mma16816(s[nb16 * 2 + 1], afr[4+u4][0], afr[4+u4][1], afr[4+u4][2], afr[4+u4][3], r1, r3);
            }
        }
        // K lo: Qhi*Klo
#pragma unroll
        for (int u4 = 0; u4 < 4; u4++) {
#pragma unroll
            for (int nb16 = 0; nb16 < 8; nb16++) {
                uint32_t r0, r1, r2, r3;
                ldmat4(r0, r1, r2, r3,
                       sk + (nb16 * 16 + lmrow) * TROW + (8 + u4 * 2 + lmunit) * 16);
                mma16816(s[nb16 * 2],     afr[u4][0], afr[u4][1], afr[u4][2], afr[u4][3], r0, r2);
                mma16816(s[nb16 * 2 + 1], afr[u4][0], afr[u4][1], afr[u4][2], afr[u4][3], r1, r3);
            }
        }

        // ---- scale + mask + online softmax ----
        float mx0 = -INFINITY, mx1 = -INFINITY;
#pragma unroll
        for (int nb = 0; nb < 16; nb++) {
            const int col = kt * 128 + nb * 8 + it * 2;
            float2 m0 = *(const float2*)(mrow0 + col);
            float2 m1 = *(const float2*)(mrow1 + col);
            s[nb][0] = fmaf(s[nb][0], 0.125f, m0.x);
            s[nb][1] = fmaf(s[nb][1], 0.125f, m0.y);
            s[nb][2] = fmaf(s[nb][2], 0.125f, m1.x);
            s[nb][3] = fmaf(s[nb][3], 0.125f, m1.y);
            mx0 = fmaxf(mx0, fmaxf(s[nb][0], s[nb][1]));
            mx1 = fmaxf(mx1, fmaxf(s[nb][2], s[nb][3]));
        }
        mx0 = fmaxf(mx0, __shfl_xor_sync(0xffffffffu, mx0, 1));
        mx0 = fmaxf(mx0, __shfl_xor_sync(0xffffffffu, mx0, 2));
        mx1 = fmaxf(mx1, __shfl_xor_sync(0xffffffffu, mx1, 1));
        mx1 = fmaxf(mx1, __shfl_xor_sync(0xffffffffu, mx1, 2));

        const float nm0 = fmaxf(mst0, mx0), nm1 = fmaxf(mst1, mx1);
        const float corr0 = __expf(mst0 - nm0), corr1 = __expf(mst1 - nm1);
        mst0 = nm0; mst1 = nm1;

        uint32_t phi[32], plo[32];
        float sum0 = 0.f, sum1 = 0.f;
#pragma unroll
        for (int nb = 0; nb < 16; nb++) {
            float p0 = __expf(s[nb][0] - nm0);
            float p1 = __expf(s[nb][1] - nm0);
            float p2 = __expf(s[nb][2] - nm1);
            float p3 = __expf(s[nb][3] - nm1);
            sum0 += p0 + p1; sum1 += p2 + p3;
            float h0 = __bfloat162float(__float2bfloat16_rn(p0));
            float h1 = __bfloat162float(__float2bfloat16_rn(p1));
            float h2 = __bfloat162float(__float2bfloat16_rn(p2));
            float h3 = __bfloat162float(__float2bfloat16_rn(p3));
            const int kk = nb >> 1;
            const int base = kk * 4 + (nb & 1) * 2;
            phi[base]     = pack_bf2(h0, h1);
            phi[base + 1] = pack_bf2(h2, h3);
            plo[base]     = pack_bf2(p0 - h0, p1 - h1);
            plo[base + 1] = pack_bf2(p2 - h2, p3 - h3);
        }
        sum0 += __shfl_xor_sync(0xffffffffu, sum0, 1);
        sum0 += __shfl_xor_sync(0xffffffffu, sum0, 2);
        sum1 += __shfl_xor_sync(0xffffffffu, sum1, 1);
        sum1 += __shfl_xor_sync(0xffffffffu, sum1, 2);
        l0 = l0 * corr0 + sum0;
        l1 = l1 * corr1 + sum1;
#pragma unroll
        for (int dn = 0; dn < 8; dn++) {
            o[dn][0] *= corr0; o[dn][1] *= corr0;
            o[dn][2] *= corr1; o[dn][3] *= corr1;
        }

        // ---- O += 3-term P V  (V-hi frags shared by phi*Vhi & plo*Vhi) ----
#pragma unroll
        for (int kk = 0; kk < 8; kk++) {
            const uint32_t* ah = phi + kk * 4;
            const uint32_t* al = plo + kk * 4;
#pragma unroll
            for (int dn16 = 0; dn16 < 4; dn16++) {
                uint32_t r0, r1, r2, r3;
                ldmat4t(r0, r1, r2, r3,
                        sv + (kk * 16 + lmrow) * TROW + (dn16 * 2 + lmunit) * 16);
                mma16816(o[dn16 * 2],     ah[0], ah[1], ah[2], ah[3], r0, r1);
                mma16816(o[dn16 * 2 + 1], ah[0], ah[1], ah[2], ah[3], r2, r3);
                mma16816(o[dn16 * 2],     al[0], al[1], al[2], al[3], r0, r1);
                mma16816(o[dn16 * 2 + 1], al[0], al[1], al[2], al[3], r2, r3);
            }
#pragma unroll
            for (int dn16 = 0; dn16 < 4; dn16++) {
                uint32_t r0, r1, r2, r3;
                ldmat4t(r0, r1, r2, r3,
                        sv + (kk * 16 + lmrow) * TROW + (8 + dn16 * 2 + lmunit) * 16);
                mma16816(o[dn16 * 2],     ah[0], ah[1], ah[2], ah[3], r0, r1);
                mma16816(o[dn16 * 2 + 1], ah[0], ah[1], ah[2], ah[3], r2, r3);
            }
        }
    }

    // ---- epilogue: normalize, split hi/lo, write A2-format ----
    const float inv0 = 1.f / l0, inv1 = 1.f / l1;
    const size_t row0 = brow + q0 + wid * 16 + g;
#pragma unroll
    for (int dn = 0; dn < 8; dn++) {
        const int col = h * 64 + dn * 8 + it * 2;
        float v0 = o[dn][0] * inv0, v1 = o[dn][1] * inv0;
        float v2 = o[dn][2] * inv1, v3 = o[dn][3] * inv1;
        __nv_bfloat16 h0 = __float2bfloat16_rn(v0), h1 = __float2bfloat16_rn(v1);
        __nv_bfloat16 h2 = __float2bfloat16_rn(v2), h3 = __float2bfloat16_rn(v3);
        __nv_bfloat162 hi01; hi01.x = h0; hi01.y = h1;
        __nv_bfloat162 hi23; hi23.x = h2; hi23.y = h3;
        __nv_bfloat162 lo01, lo23;
        lo01.x = __float2bfloat16_rn(v0 - __bfloat162float(h0));
        lo01.y = __float2bfloat16_rn(v1 - __bfloat162float(h1));
        lo23.x = __float2bfloat16_rn(v2 - __bfloat162float(h2));
        lo23.y = __float2bfloat16_rn(v3 - __bfloat162float(h3));
        __nv_bfloat16* p0 = Aout + row0 * 2048 + col;
        __nv_bfloat16* p1 = Aout + (row0 + 8) * 2048 + col;
        *(__nv_bfloat162*)p0 = hi01;
        *(__nv_bfloat162*)(p0 + 1024) = lo01;
        *(__nv_bfloat162*)p1 = hi23;
        *(__nv_bfloat162*)(p1 + 1024) = lo23;
    }
}

// ---------------- launch ----------------
extern "C" void kernel_launch(void* const* d_in, const int* in_sizes, int n_in,
                              void* d_out, int out_size) {
    (void)in_sizes; (void)n_in; (void)out_size;
    const float* hidden = (const float*)d_in[0];
    const float* mask   = (const float*)d_in[1];
    const float* qs = (const float*)d_in[2];
    const float* qd = (const float*)d_in[3];
    const float* ks = (const float*)d_in[4];
    const float* kd = (const float*)d_in[5];
    const float* vs = (const float*)d_in[6];
    const float* vd = (const float*)d_in[7];
    const float* os = (const float*)d_in[8];
    const float* od = (const float*)d_in[9];

    __nv_bfloat16 *a2, *wq2, *wk2, *wv2, *wo2, *q2, *k2, *v2;
    cudaGetSymbolAddress((void**)&a2,  g_a2);
    cudaGetSymbolAddress((void**)&wq2, g_wq2);
    cudaGetSymbolAddress((void**)&wk2, g_wk2);
    cudaGetSymbolAddress((void**)&wv2, g_wv2);
    cudaGetSymbolAddress((void**)&wo2, g_wo2);
    cudaGetSymbolAddress((void**)&q2,  g_q2);
    cudaGetSymbolAddress((void**)&k2,  g_k2);
    cudaGetSymbolAddress((void**)&v2,  g_v2);

    cudaFuncSetAttribute(tc_gemm<0>, cudaFuncAttributeMaxDynamicSharedMemorySize, 3 * STAGEB);
    cudaFuncSetAttribute(tc_gemm<1>, cudaFuncAttributeMaxDynamicSharedMemorySize, 3 * STAGEB);
    cudaFuncSetAttribute(attn_tc, cudaFuncAttributeMaxDynamicSharedMemorySize, ATTN_SMEM);

    // hi/lo splits
    split_kernel<<<MM, 256>>>(hidden, nullptr, a2);
    wsplit4_kernel<<<dim3(1024, 4), 256>>>(qs, qd, ks, kd, vs, vd, os, od,
                                           wq2, wk2, wv2, wo2);

    // Q,K,V projections -> per-head split bf16
    tc_gemm<1><<<dim3(8, 32, 3), 256, 3 * STAGEB>>>(a2, wq2, wk2, wv2, q2, k2, v2);

    // attention -> writes A2-format split directly into g_a2 (reused)
    attn_tc<<<dim3(SS / 128, NHH, BB), 256, ATTN_SMEM>>>(mask, q2, k2, v2, a2);

    // O projection -> fp32 d_out
    tc_gemm<0><<<dim3(8, 32, 1), 256, 3 * STAGEB>>>(a2, wo2, wo2, wo2,
                                                    d_out, d_out, d_out);
}